// round 2
// baseline (speedup 1.0000x reference)
#include <cuda_runtime.h>
#include <cuda_bf16.h>
#include <cstdint>

#define N_NODES   100000
#define N_EDGES   3200000
#define N_FEAT    128
#define HIDDEN    16
#define N_CLASSES 10
#define N_GRAPHS  512

// ---------------- scratch (static __device__; no allocation) ----------------
__device__ __align__(16) int   g_es[N_EDGES];
__device__ __align__(16) int   g_ed[N_EDGES];
__device__ __align__(16) float g_w[N_EDGES];
__device__ __align__(16) int   g_deg[N_NODES];
__device__ __align__(16) float g_dinv[N_NODES];
__device__ __align__(16) float g_h[2][N_NODES * HIDDEN];
__device__ __align__(16) float g_agg[2][N_NODES * HIDDEN];
__device__ __align__(16) float g_pooled[N_GRAPHS * HIDDEN];
__device__ int g_is64;

// ---------------- helpers ----------------
__device__ __forceinline__ void red_add_v4(float4* addr, float4 v) {
    asm volatile("red.global.add.v4.f32 [%0], {%1,%2,%3,%4};"
                 :: "l"(addr), "f"(v.x), "f"(v.y), "f"(v.z), "f"(v.w)
                 : "memory");
}

// Read index j from an array that is either int64 or int32, per g_is64.
__device__ __forceinline__ int read_idx(const void* p, long long j) {
    if (g_is64) return (int)((const long long*)p)[j];
    return ((const int*)p)[j];
}

// ---------------- kernels ----------------

// Detect whether edge_index is int64 (odd int32 words all zero) or int32.
__global__ void k_detect(const int* __restrict__ ei32) {
    if (threadIdx.x == 0 && blockIdx.x == 0) {
        int ok = 1;
        for (int i = 1; i < 128; i += 2)
            if (ei32[i] != 0) { ok = 0; break; }
        g_is64 = ok;
    }
}

// deg[n] = 1 (self loop)
__global__ void k_deg_init() {
    int n = blockIdx.x * blockDim.x + threadIdx.x;
    if (n < N_NODES) g_deg[n] = 1;
}

// deg[dst] += 1 over edges
__global__ void k_deg_count(const void* __restrict__ ei) {
    int e = blockIdx.x * blockDim.x + threadIdx.x;
    if (e >= N_EDGES) return;
    int d = read_idx(ei, (long long)N_EDGES + e);
    if ((unsigned)d < N_NODES) atomicAdd(&g_deg[d], 1);
}

// dinv[n] = rsqrt(deg)
__global__ void k_dinv() {
    int n = blockIdx.x * blockDim.x + threadIdx.x;
    if (n < N_NODES) g_dinv[n] = rsqrtf((float)g_deg[n]);
}

// pack int32 edges + per-edge norm
__global__ void k_prep(const void* __restrict__ ei) {
    int e = blockIdx.x * blockDim.x + threadIdx.x;
    if (e >= N_EDGES) return;
    int s = read_idx(ei, e);
    int d = read_idx(ei, (long long)N_EDGES + e);
    if ((unsigned)s >= N_NODES) s = 0;
    if ((unsigned)d >= N_NODES) d = 0;
    g_es[e] = s;
    g_ed[e] = d;
    g_w[e]  = g_dinv[s] * g_dinv[d];
}

// h1 = x @ W1 ; agg1 = dinv^2 * h1 (self-loop init). 16 threads per node.
__global__ void k_gemm1(const float* __restrict__ x, const float* __restrict__ W1) {
    __shared__ float Ws[N_FEAT * HIDDEN];
    for (int i = threadIdx.x; i < N_FEAT * HIDDEN; i += blockDim.x) Ws[i] = W1[i];
    __syncthreads();
    int idx = blockIdx.x * blockDim.x + threadIdx.x;
    int n = idx >> 4, f = idx & 15;
    if (n >= N_NODES) return;
    const float4* xr = (const float4*)(x + (size_t)n * N_FEAT);
    float s = 0.f;
#pragma unroll
    for (int k = 0; k < N_FEAT / 4; k++) {
        float4 v = xr[k];
        s += v.x * Ws[(4 * k + 0) * HIDDEN + f];
        s += v.y * Ws[(4 * k + 1) * HIDDEN + f];
        s += v.z * Ws[(4 * k + 2) * HIDDEN + f];
        s += v.w * Ws[(4 * k + 3) * HIDDEN + f];
    }
    float di = g_dinv[n];
    g_h[0][n * HIDDEN + f]   = s;
    g_agg[0][n * HIDDEN + f] = di * di * s;
}

// agg[dst] += w * h[src]  (4x float4 vector reductions per edge)
__global__ void k_scatter(int cur) {
    int e = blockIdx.x * blockDim.x + threadIdx.x;
    if (e >= N_EDGES) return;
    int s = g_es[e];
    int d = g_ed[e];
    float wt = g_w[e];
    const float4* hr = (const float4*)&g_h[cur][s * HIDDEN];
    float4* ag = (float4*)&g_agg[cur][d * HIDDEN];
#pragma unroll
    for (int q = 0; q < 4; q++) {
        float4 v = hr[q];
        v.x *= wt; v.y *= wt; v.z *= wt; v.w *= wt;
        red_add_v4(ag + q, v);
    }
}

// t = relu(agg + bias); h_next = t @ Wnext; agg_next = dinv^2 * h_next
__global__ void k_update(int cur, const float* __restrict__ bias,
                         const float* __restrict__ Wn) {
    __shared__ float Ws[HIDDEN * HIDDEN];
    __shared__ float bs[HIDDEN];
    int t = threadIdx.x;
    if (t < HIDDEN * HIDDEN) Ws[t] = Wn[t];
    if (t < HIDDEN) bs[t] = bias[t];
    __syncthreads();
    int idx = blockIdx.x * blockDim.x + t;
    int n = idx >> 4, g = idx & 15;
    if (n >= N_NODES) return;
    const float4* ar = (const float4*)&g_agg[cur][n * HIDDEN];
    float acc = 0.f;
#pragma unroll
    for (int q = 0; q < 4; q++) {
        float4 a = ar[q];
        float t0 = fmaxf(a.x + bs[4 * q + 0], 0.f);
        float t1 = fmaxf(a.y + bs[4 * q + 1], 0.f);
        float t2 = fmaxf(a.z + bs[4 * q + 2], 0.f);
        float t3 = fmaxf(a.w + bs[4 * q + 3], 0.f);
        acc += t0 * Ws[(4 * q + 0) * HIDDEN + g];
        acc += t1 * Ws[(4 * q + 1) * HIDDEN + g];
        acc += t2 * Ws[(4 * q + 2) * HIDDEN + g];
        acc += t3 * Ws[(4 * q + 3) * HIDDEN + g];
    }
    int nxt = 1 - cur;
    float di = g_dinv[n];
    g_h[nxt][n * HIDDEN + g]   = acc;
    g_agg[nxt][n * HIDDEN + g] = di * di * acc;
}

__global__ void k_zero_pooled() {
    int i = blockIdx.x * blockDim.x + threadIdx.x;
    if (i < N_GRAPHS * HIDDEN) g_pooled[i] = 0.f;
}

// pooled[batch[n]] += agg3[n] + b3   (no relu on last conv)
__global__ void k_pool(int cur, const float* __restrict__ b3,
                       const void* __restrict__ batch) {
    int idx = blockIdx.x * blockDim.x + threadIdx.x;
    int n = idx >> 2, q = idx & 3;
    if (n >= N_NODES) return;
    float4 v = ((const float4*)&g_agg[cur][n * HIDDEN])[q];
    float4 bb = ((const float4*)b3)[q];
    v.x += bb.x; v.y += bb.y; v.z += bb.z; v.w += bb.w;
    int gph = read_idx(batch, n);
    if ((unsigned)gph < N_GRAPHS)
        red_add_v4((float4*)&g_pooled[gph * HIDDEN + q * 4], v);
}

// out[g][c] = pooled[g] @ Wlin + blin
__global__ void k_head(const float* __restrict__ Wlin,
                       const float* __restrict__ blin, float* __restrict__ out) {
    int idx = blockIdx.x * blockDim.x + threadIdx.x;
    if (idx >= N_GRAPHS * N_CLASSES) return;
    int g = idx / N_CLASSES, c = idx % N_CLASSES;
    float s = blin[c];
#pragma unroll
    for (int f = 0; f < HIDDEN; f++)
        s += g_pooled[g * HIDDEN + f] * Wlin[f * N_CLASSES + c];
    out[idx] = s;
}

// ---------------- launch ----------------
extern "C" void kernel_launch(void* const* d_in, const int* in_sizes, int n_in,
                              void* d_out, int out_size) {
    const float* x     = (const float*)d_in[0];
    const void*  ei    = d_in[1];
    const void*  batch = d_in[2];
    const float* W1    = (const float*)d_in[3];
    const float* b1    = (const float*)d_in[4];
    const float* W2    = (const float*)d_in[5];
    const float* b2    = (const float*)d_in[6];
    const float* W3    = (const float*)d_in[7];
    const float* b3    = (const float*)d_in[8];
    const float* Wlin  = (const float*)d_in[9];
    const float* blin  = (const float*)d_in[10];
    float* out = (float*)d_out;

    const int T = 256;
    int gN   = (N_NODES + T - 1) / T;
    int gE   = (N_EDGES + T - 1) / T;
    int gNH  = (N_NODES * HIDDEN + T - 1) / T;
    int gN4  = (N_NODES * 4 + T - 1) / T;

    k_detect<<<1, 32>>>((const int*)ei);
    k_deg_init<<<gN, T>>>();
    k_deg_count<<<gE, T>>>(ei);
    k_dinv<<<gN, T>>>();
    k_prep<<<gE, T>>>(ei);

    k_gemm1<<<gNH, T>>>(x, W1);
    k_scatter<<<gE, T>>>(0);
    k_update<<<gNH, T>>>(0, b1, W2);
    k_scatter<<<gE, T>>>(1);
    k_update<<<gNH, T>>>(1, b2, W3);
    k_scatter<<<gE, T>>>(0);

    k_zero_pooled<<<(N_GRAPHS * HIDDEN + T - 1) / T, T>>>();
    k_pool<<<gN4, T>>>(0, b3, batch);
    k_head<<<(N_GRAPHS * N_CLASSES + T - 1) / T, T>>>(Wlin, blin, out);
}

// round 3
// speedup vs baseline: 1.7294x; 1.7294x over previous
#include <cuda_runtime.h>
#include <cuda_bf16.h>
#include <cstdint>

#define N_NODES   100000
#define N_EDGES   3200000
#define N_FEAT    128
#define HIDDEN    16
#define N_CLASSES 10
#define N_GRAPHS  512

#define SCAN_B 1024
#define NBLK   ((N_NODES + SCAN_B - 1) / SCAN_B)

// ---------------- scratch (static __device__; no allocation) ----------------
__device__ __align__(16) int2  g_csr[N_EDGES];        // {src, w-as-int}
__device__ __align__(16) int   g_off[N_NODES + 1];
__device__ __align__(16) int   g_cursor[N_NODES];
__device__ __align__(16) int   g_cnt[N_NODES];
__device__ __align__(16) int   g_bsum[NBLK];
__device__ __align__(16) float g_dinv[N_NODES];
__device__ __align__(16) float g_h[2][N_NODES * HIDDEN];
__device__ __align__(16) float g_agg[N_NODES * HIDDEN];
__device__ __align__(16) float g_pooled[N_GRAPHS * HIDDEN];
__device__ int g_is64;

// ---------------- helpers ----------------
__device__ __forceinline__ void red_add_v4(float4* addr, float4 v) {
    asm volatile("red.global.add.v4.f32 [%0], {%1,%2,%3,%4};"
                 :: "l"(addr), "f"(v.x), "f"(v.y), "f"(v.z), "f"(v.w)
                 : "memory");
}

__device__ __forceinline__ int read_idx(const void* p, long long j) {
    if (g_is64) return (int)((const long long*)p)[j];
    return ((const int*)p)[j];
}

// ---------------- preprocessing kernels ----------------

// Detect whether edge_index is int64 (odd int32 words all zero) or int32.
__global__ void k_detect(const int* __restrict__ ei32) {
    if (threadIdx.x == 0 && blockIdx.x == 0) {
        int ok = 1;
        for (int i = 1; i < 128; i += 2)
            if (ei32[i] != 0) { ok = 0; break; }
        g_is64 = ok;
    }
}

__global__ void k_cnt_zero() {
    int n = blockIdx.x * blockDim.x + threadIdx.x;
    if (n < N_NODES) g_cnt[n] = 0;
}

// cnt[dst] += 1 over edges (in-degree excluding self-loop)
__global__ void k_count(const void* __restrict__ ei) {
    int e = blockIdx.x * blockDim.x + threadIdx.x;
    if (e >= N_EDGES) return;
    int d = read_idx(ei, (long long)N_EDGES + e);
    if ((unsigned)d < N_NODES) atomicAdd(&g_cnt[d], 1);
}

// dinv[n] = rsqrt(cnt + 1)   (self-loop included in degree)
__global__ void k_dinv() {
    int n = blockIdx.x * blockDim.x + threadIdx.x;
    if (n < N_NODES) g_dinv[n] = rsqrtf((float)(g_cnt[n] + 1));
}

// 2-level exclusive scan of cnt -> off
__global__ void k_scan1() {
    __shared__ int sh[SCAN_B];
    int i = blockIdx.x * SCAN_B + threadIdx.x;
    int v = (i < N_NODES) ? g_cnt[i] : 0;
    sh[threadIdx.x] = v;
    __syncthreads();
#pragma unroll
    for (int off = 1; off < SCAN_B; off <<= 1) {
        int t = (threadIdx.x >= off) ? sh[threadIdx.x - off] : 0;
        __syncthreads();
        sh[threadIdx.x] += t;
        __syncthreads();
    }
    if (i < N_NODES) g_off[i] = sh[threadIdx.x] - v;   // local exclusive
    if (threadIdx.x == SCAN_B - 1) g_bsum[blockIdx.x] = sh[threadIdx.x];
}

__global__ void k_scan2() {
    if (threadIdx.x == 0 && blockIdx.x == 0) {
        int run = 0;
        for (int b = 0; b < NBLK; b++) { int t = g_bsum[b]; g_bsum[b] = run; run += t; }
    }
}

__global__ void k_scan3() {
    int i = blockIdx.x * blockDim.x + threadIdx.x;
    if (i < N_NODES) {
        int o = g_off[i] + g_bsum[i / SCAN_B];
        g_off[i] = o;
        g_cursor[i] = o;
    }
    if (i == 0) g_off[N_NODES] = N_EDGES;
}

// scatter edges into CSR buckets (order within bucket arbitrary; sum commutes)
__global__ void k_fill(const void* __restrict__ ei) {
    int e = blockIdx.x * blockDim.x + threadIdx.x;
    if (e >= N_EDGES) return;
    int s = read_idx(ei, e);
    int d = read_idx(ei, (long long)N_EDGES + e);
    if ((unsigned)s >= N_NODES) s = 0;
    if ((unsigned)d >= N_NODES) d = 0;
    int pos = atomicAdd(&g_cursor[d], 1);
    float w = g_dinv[s] * g_dinv[d];
    g_csr[pos] = make_int2(s, __float_as_int(w));
}

// ---------------- compute kernels ----------------

// h0 = x @ W1. 16 threads per node.
__global__ void k_gemm1(const float* __restrict__ x, const float* __restrict__ W1) {
    __shared__ float Ws[N_FEAT * HIDDEN];
    for (int i = threadIdx.x; i < N_FEAT * HIDDEN; i += blockDim.x) Ws[i] = W1[i];
    __syncthreads();
    int idx = blockIdx.x * blockDim.x + threadIdx.x;
    int n = idx >> 4, f = idx & 15;
    if (n >= N_NODES) return;
    const float4* xr = (const float4*)(x + (size_t)n * N_FEAT);
    float s = 0.f;
#pragma unroll
    for (int k = 0; k < N_FEAT / 4; k++) {
        float4 v = xr[k];
        s += v.x * Ws[(4 * k + 0) * HIDDEN + f];
        s += v.y * Ws[(4 * k + 1) * HIDDEN + f];
        s += v.z * Ws[(4 * k + 2) * HIDDEN + f];
        s += v.w * Ws[(4 * k + 3) * HIDDEN + f];
    }
    g_h[0][n * HIDDEN + f] = s;
}

// agg[n] = dinv^2 * h[n] + sum_{e in CSR(n)} w_e * h[src_e]
// 4 lanes per node, each owns one float4 of the 16 features.
__global__ void k_aggregate(int cur) {
    int idx = blockIdx.x * blockDim.x + threadIdx.x;
    int n = idx >> 2, q = idx & 3;
    if (n >= N_NODES) return;
    const float4* h4 = (const float4*)g_h[cur];
    float di = g_dinv[n];
    float4 hv = h4[n * 4 + q];
    float s2 = di * di;
    float4 acc;
    acc.x = s2 * hv.x; acc.y = s2 * hv.y; acc.z = s2 * hv.z; acc.w = s2 * hv.w;
    int beg = g_off[n], end = g_off[n + 1];
    for (int e = beg; e < end; e++) {
        int2 sw = g_csr[e];
        float w = __int_as_float(sw.y);
        float4 v = h4[sw.x * 4 + q];
        acc.x += w * v.x; acc.y += w * v.y; acc.z += w * v.z; acc.w += w * v.w;
    }
    ((float4*)g_agg)[n * 4 + q] = acc;
}

// t = relu(agg + bias); h_next = t @ Wnext
__global__ void k_update(int nxt, const float* __restrict__ bias,
                         const float* __restrict__ Wn) {
    __shared__ float Ws[HIDDEN * HIDDEN];
    __shared__ float bs[HIDDEN];
    int t = threadIdx.x;
    if (t < HIDDEN * HIDDEN) Ws[t] = Wn[t];
    if (t < HIDDEN) bs[t] = bias[t];
    __syncthreads();
    int idx = blockIdx.x * blockDim.x + t;
    int n = idx >> 4, g = idx & 15;
    if (n >= N_NODES) return;
    const float4* ar = (const float4*)&g_agg[n * HIDDEN];
    float acc = 0.f;
#pragma unroll
    for (int q = 0; q < 4; q++) {
        float4 a = ar[q];
        float t0 = fmaxf(a.x + bs[4 * q + 0], 0.f);
        float t1 = fmaxf(a.y + bs[4 * q + 1], 0.f);
        float t2 = fmaxf(a.z + bs[4 * q + 2], 0.f);
        float t3 = fmaxf(a.w + bs[4 * q + 3], 0.f);
        acc += t0 * Ws[(4 * q + 0) * HIDDEN + g];
        acc += t1 * Ws[(4 * q + 1) * HIDDEN + g];
        acc += t2 * Ws[(4 * q + 2) * HIDDEN + g];
        acc += t3 * Ws[(4 * q + 3) * HIDDEN + g];
    }
    g_h[nxt][n * HIDDEN + g] = acc;
}

__global__ void k_zero_pooled() {
    int i = blockIdx.x * blockDim.x + threadIdx.x;
    if (i < N_GRAPHS * HIDDEN) g_pooled[i] = 0.f;
}

// pooled[batch[n]] += agg3[n] + b3
__global__ void k_pool(const float* __restrict__ b3, const void* __restrict__ batch) {
    int idx = blockIdx.x * blockDim.x + threadIdx.x;
    int n = idx >> 2, q = idx & 3;
    if (n >= N_NODES) return;
    float4 v = ((const float4*)&g_agg[n * HIDDEN])[q];
    float4 bb = ((const float4*)b3)[q];
    v.x += bb.x; v.y += bb.y; v.z += bb.z; v.w += bb.w;
    int gph = read_idx(batch, n);
    if ((unsigned)gph < N_GRAPHS)
        red_add_v4((float4*)&g_pooled[gph * HIDDEN + q * 4], v);
}

// out[g][c] = pooled[g] @ Wlin + blin
__global__ void k_head(const float* __restrict__ Wlin,
                       const float* __restrict__ blin, float* __restrict__ out) {
    int idx = blockIdx.x * blockDim.x + threadIdx.x;
    if (idx >= N_GRAPHS * N_CLASSES) return;
    int g = idx / N_CLASSES, c = idx % N_CLASSES;
    float s = blin[c];
#pragma unroll
    for (int f = 0; f < HIDDEN; f++)
        s += g_pooled[g * HIDDEN + f] * Wlin[f * N_CLASSES + c];
    out[idx] = s;
}

// ---------------- launch ----------------
extern "C" void kernel_launch(void* const* d_in, const int* in_sizes, int n_in,
                              void* d_out, int out_size) {
    const float* x     = (const float*)d_in[0];
    const void*  ei    = d_in[1];
    const void*  batch = d_in[2];
    const float* W1    = (const float*)d_in[3];
    const float* b1    = (const float*)d_in[4];
    const float* W2    = (const float*)d_in[5];
    const float* b2    = (const float*)d_in[6];
    const float* W3    = (const float*)d_in[7];
    const float* b3    = (const float*)d_in[8];
    const float* Wlin  = (const float*)d_in[9];
    const float* blin  = (const float*)d_in[10];
    float* out = (float*)d_out;

    const int T = 256;
    int gN   = (N_NODES + T - 1) / T;
    int gE   = (N_EDGES + T - 1) / T;
    int gNH  = (N_NODES * HIDDEN + T - 1) / T;
    int gN4  = (N_NODES * 4 + T - 1) / T;

    // ---- CSR build (per call; deterministic work) ----
    k_detect<<<1, 32>>>((const int*)ei);
    k_cnt_zero<<<gN, T>>>();
    k_count<<<gE, T>>>(ei);
    k_dinv<<<gN, T>>>();
    k_scan1<<<NBLK, SCAN_B>>>();
    k_scan2<<<1, 32>>>();
    k_scan3<<<gN, T>>>();
    k_fill<<<gE, T>>>(ei);

    // ---- 3-layer GCN ----
    k_gemm1<<<gNH, T>>>(x, W1);
    k_aggregate<<<gN4, T>>>(0);
    k_update<<<gNH, T>>>(1, b1, W2);
    k_aggregate<<<gN4, T>>>(1);
    k_update<<<gNH, T>>>(0, b2, W3);
    k_aggregate<<<gN4, T>>>(0);

    // ---- pool + head ----
    k_zero_pooled<<<(N_GRAPHS * HIDDEN + T - 1) / T, T>>>();
    k_pool<<<gN4, T>>>(b3, batch);
    k_head<<<(N_GRAPHS * N_CLASSES + T - 1) / T, T>>>(Wlin, blin, out);
}

// round 4
// speedup vs baseline: 2.0929x; 1.2102x over previous
#include <cuda_runtime.h>
#include <cuda_bf16.h>
#include <cstdint>

#define N_NODES   100000
#define N_EDGES   3200000
#define N_FEAT    128
#define HIDDEN    16
#define N_CLASSES 10
#define N_GRAPHS  512

#define SCAN_B 1024
#define NBLK   ((N_NODES + SCAN_B - 1) / SCAN_B)   // 98

// ---------------- scratch (static __device__; no allocation) ----------------
__device__ __align__(16) int2  g_csr[N_EDGES];        // {src, w-as-int}
__device__ __align__(16) int   g_off[N_NODES + 1];
__device__ __align__(16) int   g_cursor[N_NODES];
__device__ __align__(16) int   g_cnt[N_NODES];
__device__ __align__(16) int   g_bsum[NBLK];
__device__ __align__(16) float g_dinv[N_NODES];
__device__ __align__(16) float g_h[2][N_NODES * HIDDEN];
__device__ __align__(16) float g_pooled[N_GRAPHS * HIDDEN];
__device__ int g_is64;

// ---------------- helpers ----------------
__device__ __forceinline__ void red_add_v4(float4* addr, float4 v) {
    asm volatile("red.global.add.v4.f32 [%0], {%1,%2,%3,%4};"
                 :: "l"(addr), "f"(v.x), "f"(v.y), "f"(v.z), "f"(v.w)
                 : "memory");
}

__device__ __forceinline__ int read_idx(const void* p, long long j) {
    if (g_is64) return (int)((const long long*)p)[j];
    return ((const int*)p)[j];
}

// ---------------- preprocessing ----------------

// Detect whether edge_index is int64 (odd int32 words all zero) or int32.
__global__ void k_detect(const int* __restrict__ ei32) {
    if (threadIdx.x == 0 && blockIdx.x == 0) {
        int ok = 1;
        for (int i = 1; i < 128; i += 2)
            if (ei32[i] != 0) { ok = 0; break; }
        g_is64 = ok;
    }
}

// zero cnt + pooled
__global__ void k_zero() {
    int i = blockIdx.x * blockDim.x + threadIdx.x;
    if (i < N_NODES) g_cnt[i] = 0;
    if (i < N_GRAPHS * HIDDEN) g_pooled[i] = 0.f;
}

// cnt[dst] += 1 over edges
__global__ void k_count(const void* __restrict__ ei) {
    int e = blockIdx.x * blockDim.x + threadIdx.x;
    if (e >= N_EDGES) return;
    int d = read_idx(ei, (long long)N_EDGES + e);
    if ((unsigned)d < N_NODES) atomicAdd(&g_cnt[d], 1);
}

// block-local exclusive scan of cnt -> off; also dinv = rsqrt(cnt+1)
__global__ void k_scan1() {
    __shared__ int sh[SCAN_B];
    int i = blockIdx.x * SCAN_B + threadIdx.x;
    int v = (i < N_NODES) ? g_cnt[i] : 0;
    if (i < N_NODES) g_dinv[i] = rsqrtf((float)(v + 1));
    sh[threadIdx.x] = v;
    __syncthreads();
#pragma unroll
    for (int off = 1; off < SCAN_B; off <<= 1) {
        int t = (threadIdx.x >= off) ? sh[threadIdx.x - off] : 0;
        __syncthreads();
        sh[threadIdx.x] += t;
        __syncthreads();
    }
    if (i < N_NODES) g_off[i] = sh[threadIdx.x] - v;   // local exclusive
    if (threadIdx.x == SCAN_B - 1) g_bsum[blockIdx.x] = sh[threadIdx.x];
}

// exclusive scan of the 98 block sums — one 128-thread block, parallel
__global__ void k_scan2() {
    __shared__ int sh[128];
    int i = threadIdx.x;
    int v = (i < NBLK) ? g_bsum[i] : 0;
    sh[i] = v;
    __syncthreads();
#pragma unroll
    for (int off = 1; off < 128; off <<= 1) {
        int t = (i >= off) ? sh[i - off] : 0;
        __syncthreads();
        sh[i] += t;
        __syncthreads();
    }
    if (i < NBLK) g_bsum[i] = sh[i] - v;  // exclusive
}

__global__ void k_scan3() {
    int i = blockIdx.x * blockDim.x + threadIdx.x;
    if (i < N_NODES) {
        int o = g_off[i] + g_bsum[i / SCAN_B];
        g_off[i] = o;
        g_cursor[i] = o;
    }
    if (i == 0) g_off[N_NODES] = N_EDGES;
}

// scatter edges into CSR buckets (order within bucket arbitrary; sum commutes)
__global__ void k_fill(const void* __restrict__ ei) {
    int e = blockIdx.x * blockDim.x + threadIdx.x;
    if (e >= N_EDGES) return;
    int s = read_idx(ei, e);
    int d = read_idx(ei, (long long)N_EDGES + e);
    if ((unsigned)s >= N_NODES) s = 0;
    if ((unsigned)d >= N_NODES) d = 0;
    int pos = atomicAdd(&g_cursor[d], 1);
    float w = g_dinv[s] * g_dinv[d];
    g_csr[pos] = make_int2(s, __float_as_int(w));
}

// ---------------- compute ----------------

// h0 = x @ W1. ONE thread per node: all shared W reads are uniform broadcast
// LDS.128, kernel is FFMA-bound instead of LDS-bound.
__global__ void k_gemm1(const float* __restrict__ x, const float* __restrict__ W1) {
    __shared__ float Ws[N_FEAT * HIDDEN];
    for (int i = threadIdx.x; i < N_FEAT * HIDDEN; i += blockDim.x) Ws[i] = W1[i];
    __syncthreads();
    int n = blockIdx.x * blockDim.x + threadIdx.x;
    if (n >= N_NODES) return;
    const float4* xr = (const float4*)(x + (size_t)n * N_FEAT);
    const float4* W4 = (const float4*)Ws;
    float4 a0 = make_float4(0.f, 0.f, 0.f, 0.f), a1 = a0, a2 = a0, a3 = a0;
#pragma unroll 4
    for (int k4 = 0; k4 < N_FEAT / 4; k4++) {
        float4 v = xr[k4];
#pragma unroll
        for (int c = 0; c < 4; c++) {
            float xk = (c == 0) ? v.x : (c == 1) ? v.y : (c == 2) ? v.z : v.w;
            int row = (k4 * 4 + c) * 4;
            float4 w0 = W4[row + 0], w1 = W4[row + 1], w2 = W4[row + 2], w3 = W4[row + 3];
            a0.x += xk * w0.x; a0.y += xk * w0.y; a0.z += xk * w0.z; a0.w += xk * w0.w;
            a1.x += xk * w1.x; a1.y += xk * w1.y; a1.z += xk * w1.z; a1.w += xk * w1.w;
            a2.x += xk * w2.x; a2.y += xk * w2.y; a2.z += xk * w2.z; a2.w += xk * w2.w;
            a3.x += xk * w3.x; a3.y += xk * w3.y; a3.z += xk * w3.z; a3.w += xk * w3.w;
        }
    }
    float4* ho = (float4*)&g_h[0][n * HIDDEN];
    ho[0] = a0; ho[1] = a1; ho[2] = a2; ho[3] = a3;
}

// Fused: agg = dinv^2*h[n] + sum_e w*h[src]; t = relu(agg + b); h_next = t @ W.
// 4 lanes/node; GEMM via 4-lane shuffle exchange + shared W.
__global__ void k_agg_update(int cur, int nxt, const float* __restrict__ bias,
                             const float* __restrict__ Wn) {
    __shared__ float Ws[HIDDEN * HIDDEN];
    __shared__ float bs[HIDDEN];
    int t = threadIdx.x;
    if (t < HIDDEN * HIDDEN) Ws[t] = Wn[t];
    if (t < HIDDEN) bs[t] = bias[t];
    __syncthreads();
    int idx = blockIdx.x * blockDim.x + t;
    int n = idx >> 2, q = idx & 3;
    if (n >= N_NODES) return;               // whole-warp granularity (400000 % 32 == 0)
    const float4* h4 = (const float4*)g_h[cur];
    float di = g_dinv[n];
    float4 hv = h4[n * 4 + q];
    float s2 = di * di;
    float4 acc;
    acc.x = s2 * hv.x; acc.y = s2 * hv.y; acc.z = s2 * hv.z; acc.w = s2 * hv.w;
    int beg = g_off[n], end = g_off[n + 1];
    for (int e = beg; e < end; e++) {
        int2 sw = g_csr[e];
        float w = __int_as_float(sw.y);
        float4 v = h4[sw.x * 4 + q];
        acc.x += w * v.x; acc.y += w * v.y; acc.z += w * v.z; acc.w += w * v.w;
    }
    // relu(agg + bias) for this lane's 4 features
    int gb = q * 4;
    float t0 = fmaxf(acc.x + bs[gb + 0], 0.f);
    float t1 = fmaxf(acc.y + bs[gb + 1], 0.f);
    float t2 = fmaxf(acc.z + bs[gb + 2], 0.f);
    float t3 = fmaxf(acc.w + bs[gb + 3], 0.f);
    // 16x16 GEMM: gather the other 3 lanes' features via shuffle
    float o0 = 0.f, o1 = 0.f, o2 = 0.f, o3 = 0.f;
#pragma unroll
    for (int r = 0; r < 4; r++) {
        float s0 = (r == 0) ? t0 : __shfl_xor_sync(0xffffffffu, t0, r);
        float s1 = (r == 0) ? t1 : __shfl_xor_sync(0xffffffffu, t1, r);
        float s2v = (r == 0) ? t2 : __shfl_xor_sync(0xffffffffu, t2, r);
        float s3 = (r == 0) ? t3 : __shfl_xor_sync(0xffffffffu, t3, r);
        int fb = (q ^ r) * 4;
        o0 += s0 * Ws[(fb + 0) * HIDDEN + gb + 0] + s1 * Ws[(fb + 1) * HIDDEN + gb + 0]
            + s2v * Ws[(fb + 2) * HIDDEN + gb + 0] + s3 * Ws[(fb + 3) * HIDDEN + gb + 0];
        o1 += s0 * Ws[(fb + 0) * HIDDEN + gb + 1] + s1 * Ws[(fb + 1) * HIDDEN + gb + 1]
            + s2v * Ws[(fb + 2) * HIDDEN + gb + 1] + s3 * Ws[(fb + 3) * HIDDEN + gb + 1];
        o2 += s0 * Ws[(fb + 0) * HIDDEN + gb + 2] + s1 * Ws[(fb + 1) * HIDDEN + gb + 2]
            + s2v * Ws[(fb + 2) * HIDDEN + gb + 2] + s3 * Ws[(fb + 3) * HIDDEN + gb + 2];
        o3 += s0 * Ws[(fb + 0) * HIDDEN + gb + 3] + s1 * Ws[(fb + 1) * HIDDEN + gb + 3]
            + s2v * Ws[(fb + 2) * HIDDEN + gb + 3] + s3 * Ws[(fb + 3) * HIDDEN + gb + 3];
    }
    ((float4*)&g_h[nxt][n * HIDDEN])[q] = make_float4(o0, o1, o2, o3);
}

// Fused last layer: aggregate + bias + pool (RED into pooled[batch[n]])
__global__ void k_agg_pool(int cur, const float* __restrict__ b3,
                           const void* __restrict__ batch) {
    int idx = blockIdx.x * blockDim.x + threadIdx.x;
    int n = idx >> 2, q = idx & 3;
    if (n >= N_NODES) return;
    const float4* h4 = (const float4*)g_h[cur];
    float di = g_dinv[n];
    float4 hv = h4[n * 4 + q];
    float s2 = di * di;
    float4 acc;
    acc.x = s2 * hv.x; acc.y = s2 * hv.y; acc.z = s2 * hv.z; acc.w = s2 * hv.w;
    int beg = g_off[n], end = g_off[n + 1];
    for (int e = beg; e < end; e++) {
        int2 sw = g_csr[e];
        float w = __int_as_float(sw.y);
        float4 v = h4[sw.x * 4 + q];
        acc.x += w * v.x; acc.y += w * v.y; acc.z += w * v.z; acc.w += w * v.w;
    }
    float4 bb = ((const float4*)b3)[q];
    acc.x += bb.x; acc.y += bb.y; acc.z += bb.z; acc.w += bb.w;
    int gph = read_idx(batch, n);
    if ((unsigned)gph < N_GRAPHS)
        red_add_v4((float4*)&g_pooled[gph * HIDDEN + q * 4], acc);
}

// out[g][c] = pooled[g] @ Wlin + blin
__global__ void k_head(const float* __restrict__ Wlin,
                       const float* __restrict__ blin, float* __restrict__ out) {
    int idx = blockIdx.x * blockDim.x + threadIdx.x;
    if (idx >= N_GRAPHS * N_CLASSES) return;
    int g = idx / N_CLASSES, c = idx % N_CLASSES;
    float s = blin[c];
#pragma unroll
    for (int f = 0; f < HIDDEN; f++)
        s += g_pooled[g * HIDDEN + f] * Wlin[f * N_CLASSES + c];
    out[idx] = s;
}

// ---------------- launch ----------------
extern "C" void kernel_launch(void* const* d_in, const int* in_sizes, int n_in,
                              void* d_out, int out_size) {
    const float* x     = (const float*)d_in[0];
    const void*  ei    = d_in[1];
    const void*  batch = d_in[2];
    const float* W1    = (const float*)d_in[3];
    const float* b1    = (const float*)d_in[4];
    const float* W2    = (const float*)d_in[5];
    const float* b2    = (const float*)d_in[6];
    const float* W3    = (const float*)d_in[7];
    const float* b3    = (const float*)d_in[8];
    const float* Wlin  = (const float*)d_in[9];
    const float* blin  = (const float*)d_in[10];
    float* out = (float*)d_out;

    const int T = 256;
    int gN  = (N_NODES + T - 1) / T;
    int gE  = (N_EDGES + T - 1) / T;
    int gN4 = (N_NODES * 4 + T - 1) / T;

    // ---- CSR build ----
    k_detect<<<1, 32>>>((const int*)ei);
    k_zero<<<gN, T>>>();
    k_count<<<gE, T>>>(ei);
    k_scan1<<<NBLK, SCAN_B>>>();
    k_scan2<<<1, 128>>>();
    k_scan3<<<gN, T>>>();
    k_fill<<<gE, T>>>(ei);

    // ---- 3-layer GCN ----
    k_gemm1<<<gN, T>>>(x, W1);
    k_agg_update<<<gN4, T>>>(0, 1, b1, W2);
    k_agg_update<<<gN4, T>>>(1, 0, b2, W3);
    k_agg_pool<<<gN4, T>>>(0, b3, batch);

    // ---- head ----
    k_head<<<(N_GRAPHS * N_CLASSES + T - 1) / T, T>>>(Wlin, blin, out);
}

// round 5
// speedup vs baseline: 2.1104x; 1.0084x over previous
#include <cuda_runtime.h>
#include <cuda_bf16.h>
#include <cuda_fp16.h>
#include <cstdint>

#define N_NODES   100000
#define N_EDGES   3200000
#define N_FEAT    128
#define HIDDEN    16
#define N_CLASSES 10
#define N_GRAPHS  512

#define SCAN_B 1024
#define NBLK   ((N_NODES + SCAN_B - 1) / SCAN_B)   // 98

// ---------------- scratch (static __device__; no allocation) ----------------
__device__ __align__(16) int2   g_csr[N_EDGES];        // {src, w-as-int}
__device__ __align__(16) int    g_off[N_NODES + 1];
__device__ __align__(16) int    g_cursor[N_NODES];
__device__ __align__(16) int    g_cnt[N_NODES];
__device__ __align__(16) int    g_bsum[NBLK];
__device__ __align__(16) float  g_dinv[N_NODES];
__device__ __align__(16) __half g_hh[2][N_NODES * HIDDEN];   // fp16 activations
__device__ __align__(16) float  g_pooled[N_GRAPHS * HIDDEN];
__device__ int g_is64;

// ---------------- helpers ----------------
__device__ __forceinline__ void red_add_v4(float4* addr, float4 v) {
    asm volatile("red.global.add.v4.f32 [%0], {%1,%2,%3,%4};"
                 :: "l"(addr), "f"(v.x), "f"(v.y), "f"(v.z), "f"(v.w)
                 : "memory");
}

__device__ __forceinline__ int read_idx(const void* p, long long j) {
    if (g_is64) return (int)((const long long*)p)[j];
    return ((const int*)p)[j];
}

__device__ __forceinline__ uint2 pack4(float a, float b, float c, float d) {
    __half2 lo = __floats2half2_rn(a, b), hi = __floats2half2_rn(c, d);
    uint2 r;
    r.x = *(unsigned*)&lo; r.y = *(unsigned*)&hi;
    return r;
}

__device__ __forceinline__ float4 unpack4(uint2 u) {
    __half2 lo = *(__half2*)&u.x, hi = *(__half2*)&u.y;
    float2 f0 = __half22float2(lo), f1 = __half22float2(hi);
    return make_float4(f0.x, f0.y, f1.x, f1.y);
}

// ---------------- preprocessing ----------------

__global__ void k_detect(const int* __restrict__ ei32) {
    if (threadIdx.x == 0 && blockIdx.x == 0) {
        int ok = 1;
        for (int i = 1; i < 128; i += 2)
            if (ei32[i] != 0) { ok = 0; break; }
        g_is64 = ok;
    }
}

__global__ void k_zero() {
    int i = blockIdx.x * blockDim.x + threadIdx.x;
    if (i < N_NODES) g_cnt[i] = 0;
    if (i < N_GRAPHS * HIDDEN) g_pooled[i] = 0.f;
}

__global__ void k_count(const void* __restrict__ ei) {
    int e = blockIdx.x * blockDim.x + threadIdx.x;
    if (e >= N_EDGES) return;
    int d = read_idx(ei, (long long)N_EDGES + e);
    if ((unsigned)d < N_NODES) atomicAdd(&g_cnt[d], 1);
}

__global__ void k_scan1() {
    __shared__ int sh[SCAN_B];
    int i = blockIdx.x * SCAN_B + threadIdx.x;
    int v = (i < N_NODES) ? g_cnt[i] : 0;
    if (i < N_NODES) g_dinv[i] = rsqrtf((float)(v + 1));
    sh[threadIdx.x] = v;
    __syncthreads();
#pragma unroll
    for (int off = 1; off < SCAN_B; off <<= 1) {
        int t = (threadIdx.x >= off) ? sh[threadIdx.x - off] : 0;
        __syncthreads();
        sh[threadIdx.x] += t;
        __syncthreads();
    }
    if (i < N_NODES) g_off[i] = sh[threadIdx.x] - v;
    if (threadIdx.x == SCAN_B - 1) g_bsum[blockIdx.x] = sh[threadIdx.x];
}

__global__ void k_scan2() {
    __shared__ int sh[128];
    int i = threadIdx.x;
    int v = (i < NBLK) ? g_bsum[i] : 0;
    sh[i] = v;
    __syncthreads();
#pragma unroll
    for (int off = 1; off < 128; off <<= 1) {
        int t = (i >= off) ? sh[i - off] : 0;
        __syncthreads();
        sh[i] += t;
        __syncthreads();
    }
    if (i < NBLK) g_bsum[i] = sh[i] - v;
}

__global__ void k_scan3() {
    int i = blockIdx.x * blockDim.x + threadIdx.x;
    if (i < N_NODES) {
        int o = g_off[i] + g_bsum[i / SCAN_B];
        g_off[i] = o;
        g_cursor[i] = o;
    }
    if (i == 0) g_off[N_NODES] = N_EDGES;
}

__global__ void k_fill(const void* __restrict__ ei) {
    int e = blockIdx.x * blockDim.x + threadIdx.x;
    if (e >= N_EDGES) return;
    int s = read_idx(ei, e);
    int d = read_idx(ei, (long long)N_EDGES + e);
    if ((unsigned)s >= N_NODES) s = 0;
    if ((unsigned)d >= N_NODES) d = 0;
    int pos = atomicAdd(&g_cursor[d], 1);
    float w = g_dinv[s] * g_dinv[d];
    g_csr[pos] = make_int2(s, __float_as_int(w));
}

// ---------------- compute ----------------

// h0 = x @ W1 (fp32 math, fp16 store). One thread per node.
__global__ void k_gemm1(const float* __restrict__ x, const float* __restrict__ W1) {
    __shared__ float Ws[N_FEAT * HIDDEN];
    for (int i = threadIdx.x; i < N_FEAT * HIDDEN; i += blockDim.x) Ws[i] = W1[i];
    __syncthreads();
    int n = blockIdx.x * blockDim.x + threadIdx.x;
    if (n >= N_NODES) return;
    const float4* xr = (const float4*)(x + (size_t)n * N_FEAT);
    const float4* W4 = (const float4*)Ws;
    float4 a0 = make_float4(0.f, 0.f, 0.f, 0.f), a1 = a0, a2 = a0, a3 = a0;
#pragma unroll 4
    for (int k4 = 0; k4 < N_FEAT / 4; k4++) {
        float4 v = xr[k4];
#pragma unroll
        for (int c = 0; c < 4; c++) {
            float xk = (c == 0) ? v.x : (c == 1) ? v.y : (c == 2) ? v.z : v.w;
            int row = (k4 * 4 + c) * 4;
            float4 w0 = W4[row + 0], w1 = W4[row + 1], w2 = W4[row + 2], w3 = W4[row + 3];
            a0.x += xk * w0.x; a0.y += xk * w0.y; a0.z += xk * w0.z; a0.w += xk * w0.w;
            a1.x += xk * w1.x; a1.y += xk * w1.y; a1.z += xk * w1.z; a1.w += xk * w1.w;
            a2.x += xk * w2.x; a2.y += xk * w2.y; a2.z += xk * w2.z; a2.w += xk * w2.w;
            a3.x += xk * w3.x; a3.y += xk * w3.y; a3.z += xk * w3.z; a3.w += xk * w3.w;
        }
    }
    uint2 u0 = pack4(a0.x, a0.y, a0.z, a0.w);
    uint2 u1 = pack4(a1.x, a1.y, a1.z, a1.w);
    uint2 u2 = pack4(a2.x, a2.y, a2.z, a2.w);
    uint2 u3 = pack4(a3.x, a3.y, a3.z, a3.w);
    uint4* ho = (uint4*)&g_hh[0][n * HIDDEN];
    ho[0] = make_uint4(u0.x, u0.y, u1.x, u1.y);
    ho[1] = make_uint4(u2.x, u2.y, u3.x, u3.y);
}

// Fused: agg = dinv^2*h[n] + sum_e w*h[src] (fp16 gather, fp32 accum);
// t = relu(agg+b); h_next = t @ W (via 4-lane shuffle); fp16 store.
__global__ void k_agg_update(int cur, int nxt, const float* __restrict__ bias,
                             const float* __restrict__ Wn) {
    __shared__ float Ws[HIDDEN * HIDDEN];
    __shared__ float bs[HIDDEN];
    int t = threadIdx.x;
    if (t < HIDDEN * HIDDEN) Ws[t] = Wn[t];
    if (t < HIDDEN) bs[t] = bias[t];
    __syncthreads();
    int idx = blockIdx.x * blockDim.x + t;
    int n = idx >> 2, q = idx & 3;
    if (n >= N_NODES) return;               // whole-warp exit (400000 % 32 == 0)
    const uint2* h4 = (const uint2*)g_hh[cur];
    float di = g_dinv[n];
    float4 hv = unpack4(h4[n * 4 + q]);
    float s2 = di * di;
    float4 acc;
    acc.x = s2 * hv.x; acc.y = s2 * hv.y; acc.z = s2 * hv.z; acc.w = s2 * hv.w;
    int beg = g_off[n], end = g_off[n + 1];
#pragma unroll 2
    for (int e = beg; e < end; e++) {
        int2 sw = g_csr[e];
        float w = __int_as_float(sw.y);
        float4 v = unpack4(h4[sw.x * 4 + q]);
        acc.x += w * v.x; acc.y += w * v.y; acc.z += w * v.z; acc.w += w * v.w;
    }
    int gb = q * 4;
    float t0 = fmaxf(acc.x + bs[gb + 0], 0.f);
    float t1 = fmaxf(acc.y + bs[gb + 1], 0.f);
    float t2 = fmaxf(acc.z + bs[gb + 2], 0.f);
    float t3 = fmaxf(acc.w + bs[gb + 3], 0.f);
    float o0 = 0.f, o1 = 0.f, o2 = 0.f, o3 = 0.f;
#pragma unroll
    for (int r = 0; r < 4; r++) {
        float s0 = (r == 0) ? t0 : __shfl_xor_sync(0xffffffffu, t0, r);
        float s1 = (r == 0) ? t1 : __shfl_xor_sync(0xffffffffu, t1, r);
        float s2v = (r == 0) ? t2 : __shfl_xor_sync(0xffffffffu, t2, r);
        float s3 = (r == 0) ? t3 : __shfl_xor_sync(0xffffffffu, t3, r);
        int fb = (q ^ r) * 4;
        o0 += s0 * Ws[(fb + 0) * HIDDEN + gb + 0] + s1 * Ws[(fb + 1) * HIDDEN + gb + 0]
            + s2v * Ws[(fb + 2) * HIDDEN + gb + 0] + s3 * Ws[(fb + 3) * HIDDEN + gb + 0];
        o1 += s0 * Ws[(fb + 0) * HIDDEN + gb + 1] + s1 * Ws[(fb + 1) * HIDDEN + gb + 1]
            + s2v * Ws[(fb + 2) * HIDDEN + gb + 1] + s3 * Ws[(fb + 3) * HIDDEN + gb + 1];
        o2 += s0 * Ws[(fb + 0) * HIDDEN + gb + 2] + s1 * Ws[(fb + 1) * HIDDEN + gb + 2]
            + s2v * Ws[(fb + 2) * HIDDEN + gb + 2] + s3 * Ws[(fb + 3) * HIDDEN + gb + 2];
        o3 += s0 * Ws[(fb + 0) * HIDDEN + gb + 3] + s1 * Ws[(fb + 1) * HIDDEN + gb + 3]
            + s2v * Ws[(fb + 2) * HIDDEN + gb + 3] + s3 * Ws[(fb + 3) * HIDDEN + gb + 3];
    }
    ((uint2*)&g_hh[nxt][n * HIDDEN])[q] = pack4(o0, o1, o2, o3);
}

// Fused last layer: aggregate + bias + pool (RED into pooled[batch[n]])
__global__ void k_agg_pool(int cur, const float* __restrict__ b3,
                           const void* __restrict__ batch) {
    int idx = blockIdx.x * blockDim.x + threadIdx.x;
    int n = idx >> 2, q = idx & 3;
    if (n >= N_NODES) return;
    const uint2* h4 = (const uint2*)g_hh[cur];
    float di = g_dinv[n];
    float4 hv = unpack4(h4[n * 4 + q]);
    float s2 = di * di;
    float4 acc;
    acc.x = s2 * hv.x; acc.y = s2 * hv.y; acc.z = s2 * hv.z; acc.w = s2 * hv.w;
    int beg = g_off[n], end = g_off[n + 1];
#pragma unroll 2
    for (int e = beg; e < end; e++) {
        int2 sw = g_csr[e];
        float w = __int_as_float(sw.y);
        float4 v = unpack4(h4[sw.x * 4 + q]);
        acc.x += w * v.x; acc.y += w * v.y; acc.z += w * v.z; acc.w += w * v.w;
    }
    float4 bb = ((const float4*)b3)[q];
    acc.x += bb.x; acc.y += bb.y; acc.z += bb.z; acc.w += bb.w;
    int gph = read_idx(batch, n);
    if ((unsigned)gph < N_GRAPHS)
        red_add_v4((float4*)&g_pooled[gph * HIDDEN + q * 4], acc);
}

// out[g][c] = pooled[g] @ Wlin + blin
__global__ void k_head(const float* __restrict__ Wlin,
                       const float* __restrict__ blin, float* __restrict__ out) {
    int idx = blockIdx.x * blockDim.x + threadIdx.x;
    if (idx >= N_GRAPHS * N_CLASSES) return;
    int g = idx / N_CLASSES, c = idx % N_CLASSES;
    float s = blin[c];
#pragma unroll
    for (int f = 0; f < HIDDEN; f++)
        s += g_pooled[g * HIDDEN + f] * Wlin[f * N_CLASSES + c];
    out[idx] = s;
}

// ---------------- launch ----------------
extern "C" void kernel_launch(void* const* d_in, const int* in_sizes, int n_in,
                              void* d_out, int out_size) {
    const float* x     = (const float*)d_in[0];
    const void*  ei    = d_in[1];
    const void*  batch = d_in[2];
    const float* W1    = (const float*)d_in[3];
    const float* b1    = (const float*)d_in[4];
    const float* W2    = (const float*)d_in[5];
    const float* b2    = (const float*)d_in[6];
    const float* W3    = (const float*)d_in[7];
    const float* b3    = (const float*)d_in[8];
    const float* Wlin  = (const float*)d_in[9];
    const float* blin  = (const float*)d_in[10];
    float* out = (float*)d_out;

    const int T = 256;
    int gN  = (N_NODES + T - 1) / T;
    int gE  = (N_EDGES + T - 1) / T;
    int gN4 = (N_NODES * 4 + T - 1) / T;

    // ---- CSR build ----
    k_detect<<<1, 32>>>((const int*)ei);
    k_zero<<<gN, T>>>();
    k_count<<<gE, T>>>(ei);
    k_scan1<<<NBLK, SCAN_B>>>();
    k_scan2<<<1, 128>>>();
    k_scan3<<<gN, T>>>();
    k_fill<<<gE, T>>>(ei);

    // ---- 3-layer GCN ----
    k_gemm1<<<gN, T>>>(x, W1);
    k_agg_update<<<gN4, T>>>(0, 1, b1, W2);
    k_agg_update<<<gN4, T>>>(1, 0, b2, W3);
    k_agg_pool<<<gN4, T>>>(0, b3, batch);

    // ---- head ----
    k_head<<<(N_GRAPHS * N_CLASSES + T - 1) / T, T>>>(Wlin, blin, out);
}

// round 6
// speedup vs baseline: 2.3118x; 1.0954x over previous
#include <cuda_runtime.h>
#include <cuda_bf16.h>
#include <cuda_fp16.h>
#include <cstdint>

#define N_NODES   100000
#define N_EDGES   3200000
#define N_FEAT    128
#define HIDDEN    16
#define N_CLASSES 10
#define N_GRAPHS  512

#define SCAN_B 1024
#define NBLK   ((N_NODES + SCAN_B - 1) / SCAN_B)   // 98

// ---------------- scratch (static __device__; no allocation) ----------------
__device__ __align__(16) int2   g_csr[N_EDGES];        // {src, w-as-int}
__device__ __align__(16) int    g_off[N_NODES + 1];
__device__ __align__(16) int    g_cursor[N_NODES];
__device__ __align__(16) int    g_cnt[N_NODES];
__device__ __align__(16) int    g_bsum[NBLK];
__device__ __align__(16) float  g_dinv[N_NODES];
__device__ __align__(16) __half g_hh[2][N_NODES * HIDDEN];   // fp16 activations
__device__ __align__(16) float  g_pooled[N_GRAPHS * HIDDEN];
__device__ int g_is64;

// ---------------- helpers ----------------
__device__ __forceinline__ void red_add_v4(float4* addr, float4 v) {
    asm volatile("red.global.add.v4.f32 [%0], {%1,%2,%3,%4};"
                 :: "l"(addr), "f"(v.x), "f"(v.y), "f"(v.z), "f"(v.w)
                 : "memory");
}

__device__ __forceinline__ int read_idx(const void* p, long long j) {
    if (g_is64) return (int)((const long long*)p)[j];
    return ((const int*)p)[j];
}

__device__ __forceinline__ uint2 pack4(float a, float b, float c, float d) {
    __half2 lo = __floats2half2_rn(a, b), hi = __floats2half2_rn(c, d);
    uint2 r;
    r.x = *(unsigned*)&lo; r.y = *(unsigned*)&hi;
    return r;
}

__device__ __forceinline__ float4 unpack4(uint2 u) {
    __half2 lo = *(__half2*)&u.x, hi = *(__half2*)&u.y;
    float2 f0 = __half22float2(lo), f1 = __half22float2(hi);
    return make_float4(f0.x, f0.y, f1.x, f1.y);
}

// ---------------- preprocessing ----------------

// zero cnt + pooled; thread 0 also detects int64 vs int32 edge_index
__global__ void k_zero(const int* __restrict__ ei32) {
    int i = blockIdx.x * blockDim.x + threadIdx.x;
    if (i < N_NODES) g_cnt[i] = 0;
    if (i < N_GRAPHS * HIDDEN) g_pooled[i] = 0.f;
    if (i == 0) {
        int ok = 1;
        for (int j = 1; j < 128; j += 2)
            if (ei32[j] != 0) { ok = 0; break; }
        g_is64 = ok;
    }
}

__global__ void k_count(const void* __restrict__ ei) {
    int e = blockIdx.x * blockDim.x + threadIdx.x;
    if (e >= N_EDGES) return;
    int d = read_idx(ei, (long long)N_EDGES + e);
    if ((unsigned)d < N_NODES) atomicAdd(&g_cnt[d], 1);
}

// block-local exclusive scan of cnt -> off (local); bsum; dinv = rsqrt(cnt+1)
__global__ void k_scan1() {
    __shared__ int sh[SCAN_B];
    int i = blockIdx.x * SCAN_B + threadIdx.x;
    int v = (i < N_NODES) ? g_cnt[i] : 0;
    if (i < N_NODES) g_dinv[i] = rsqrtf((float)(v + 1));
    sh[threadIdx.x] = v;
    __syncthreads();
#pragma unroll
    for (int off = 1; off < SCAN_B; off <<= 1) {
        int t = (threadIdx.x >= off) ? sh[threadIdx.x - off] : 0;
        __syncthreads();
        sh[threadIdx.x] += t;
        __syncthreads();
    }
    if (i < N_NODES) g_off[i] = sh[threadIdx.x] - v;
    if (threadIdx.x == SCAN_B - 1) g_bsum[blockIdx.x] = sh[threadIdx.x];
}

// add block prefix (each block reduces bsum[0..blockIdx) itself) ; init cursor
__global__ void k_scan3() {          // grid NBLK, SCAN_B threads
    __shared__ int tmp[32];
    __shared__ int pfx;
    int t = threadIdx.x, j = blockIdx.x;
    int v = (t < j) ? g_bsum[t] : 0;     // j <= 97 < 1024
#pragma unroll
    for (int o = 16; o; o >>= 1) v += __shfl_down_sync(0xffffffffu, v, o);
    if ((t & 31) == 0) tmp[t >> 5] = v;
    __syncthreads();
    if (t < 32) {
        int s = tmp[t];
#pragma unroll
        for (int o = 16; o; o >>= 1) s += __shfl_down_sync(0xffffffffu, s, o);
        if (t == 0) pfx = s;
    }
    __syncthreads();
    int i = j * SCAN_B + t;
    if (i < N_NODES) {
        int o = g_off[i] + pfx;
        g_off[i] = o;
        g_cursor[i] = o;
    }
    if (i == 0) g_off[N_NODES] = N_EDGES;
}

__global__ void k_fill(const void* __restrict__ ei) {
    int e = blockIdx.x * blockDim.x + threadIdx.x;
    if (e >= N_EDGES) return;
    int s = read_idx(ei, e);
    int d = read_idx(ei, (long long)N_EDGES + e);
    if ((unsigned)s >= N_NODES) s = 0;
    if ((unsigned)d >= N_NODES) d = 0;
    int pos = atomicAdd(&g_cursor[d], 1);
    float w = g_dinv[s] * g_dinv[d];
    g_csr[pos] = make_int2(s, __float_as_int(w));
}

// ---------------- compute ----------------

// h0 = x @ W1 (fp32 math, fp16 store). One thread per node. Runs on side stream.
__global__ void k_gemm1(const float* __restrict__ x, const float* __restrict__ W1) {
    __shared__ float Ws[N_FEAT * HIDDEN];
    for (int i = threadIdx.x; i < N_FEAT * HIDDEN; i += blockDim.x) Ws[i] = W1[i];
    __syncthreads();
    int n = blockIdx.x * blockDim.x + threadIdx.x;
    if (n >= N_NODES) return;
    const float4* xr = (const float4*)(x + (size_t)n * N_FEAT);
    const float4* W4 = (const float4*)Ws;
    float4 a0 = make_float4(0.f, 0.f, 0.f, 0.f), a1 = a0, a2 = a0, a3 = a0;
#pragma unroll 4
    for (int k4 = 0; k4 < N_FEAT / 4; k4++) {
        float4 v = xr[k4];
#pragma unroll
        for (int c = 0; c < 4; c++) {
            float xk = (c == 0) ? v.x : (c == 1) ? v.y : (c == 2) ? v.z : v.w;
            int row = (k4 * 4 + c) * 4;
            float4 w0 = W4[row + 0], w1 = W4[row + 1], w2 = W4[row + 2], w3 = W4[row + 3];
            a0.x += xk * w0.x; a0.y += xk * w0.y; a0.z += xk * w0.z; a0.w += xk * w0.w;
            a1.x += xk * w1.x; a1.y += xk * w1.y; a1.z += xk * w1.z; a1.w += xk * w1.w;
            a2.x += xk * w2.x; a2.y += xk * w2.y; a2.z += xk * w2.z; a2.w += xk * w2.w;
            a3.x += xk * w3.x; a3.y += xk * w3.y; a3.z += xk * w3.z; a3.w += xk * w3.w;
        }
    }
    uint2 u0 = pack4(a0.x, a0.y, a0.z, a0.w);
    uint2 u1 = pack4(a1.x, a1.y, a1.z, a1.w);
    uint2 u2 = pack4(a2.x, a2.y, a2.z, a2.w);
    uint2 u3 = pack4(a3.x, a3.y, a3.z, a3.w);
    uint4* ho = (uint4*)&g_hh[0][n * HIDDEN];
    ho[0] = make_uint4(u0.x, u0.y, u1.x, u1.y);
    ho[1] = make_uint4(u2.x, u2.y, u3.x, u3.y);
}

// Fused: agg = dinv^2*h[n] + sum_e w*h[src]; t = relu(agg+b); h_next = t @ W.
__global__ void k_agg_update(int cur, int nxt, const float* __restrict__ bias,
                             const float* __restrict__ Wn) {
    __shared__ float Ws[HIDDEN * HIDDEN];
    __shared__ float bs[HIDDEN];
    int t = threadIdx.x;
    if (t < HIDDEN * HIDDEN) Ws[t] = Wn[t];
    if (t < HIDDEN) bs[t] = bias[t];
    __syncthreads();
    int idx = blockIdx.x * blockDim.x + t;
    int n = idx >> 2, q = idx & 3;
    if (n >= N_NODES) return;               // whole-warp exit (400000 % 32 == 0)
    const uint2* h4 = (const uint2*)g_hh[cur];
    float di = g_dinv[n];
    float4 hv = unpack4(h4[n * 4 + q]);
    float s2 = di * di;
    float4 acc;
    acc.x = s2 * hv.x; acc.y = s2 * hv.y; acc.z = s2 * hv.z; acc.w = s2 * hv.w;
    int beg = g_off[n], end = g_off[n + 1];
#pragma unroll 4
    for (int e = beg; e < end; e++) {
        int2 sw = g_csr[e];
        float w = __int_as_float(sw.y);
        float4 v = unpack4(h4[sw.x * 4 + q]);
        acc.x += w * v.x; acc.y += w * v.y; acc.z += w * v.z; acc.w += w * v.w;
    }
    int gb = q * 4;
    float t0 = fmaxf(acc.x + bs[gb + 0], 0.f);
    float t1 = fmaxf(acc.y + bs[gb + 1], 0.f);
    float t2 = fmaxf(acc.z + bs[gb + 2], 0.f);
    float t3 = fmaxf(acc.w + bs[gb + 3], 0.f);
    float o0 = 0.f, o1 = 0.f, o2 = 0.f, o3 = 0.f;
#pragma unroll
    for (int r = 0; r < 4; r++) {
        float s0 = (r == 0) ? t0 : __shfl_xor_sync(0xffffffffu, t0, r);
        float s1 = (r == 0) ? t1 : __shfl_xor_sync(0xffffffffu, t1, r);
        float s2v = (r == 0) ? t2 : __shfl_xor_sync(0xffffffffu, t2, r);
        float s3 = (r == 0) ? t3 : __shfl_xor_sync(0xffffffffu, t3, r);
        int fb = (q ^ r) * 4;
        o0 += s0 * Ws[(fb + 0) * HIDDEN + gb + 0] + s1 * Ws[(fb + 1) * HIDDEN + gb + 0]
            + s2v * Ws[(fb + 2) * HIDDEN + gb + 0] + s3 * Ws[(fb + 3) * HIDDEN + gb + 0];
        o1 += s0 * Ws[(fb + 0) * HIDDEN + gb + 1] + s1 * Ws[(fb + 1) * HIDDEN + gb + 1]
            + s2v * Ws[(fb + 2) * HIDDEN + gb + 1] + s3 * Ws[(fb + 3) * HIDDEN + gb + 1];
        o2 += s0 * Ws[(fb + 0) * HIDDEN + gb + 2] + s1 * Ws[(fb + 1) * HIDDEN + gb + 2]
            + s2v * Ws[(fb + 2) * HIDDEN + gb + 2] + s3 * Ws[(fb + 3) * HIDDEN + gb + 2];
        o3 += s0 * Ws[(fb + 0) * HIDDEN + gb + 3] + s1 * Ws[(fb + 1) * HIDDEN + gb + 3]
            + s2v * Ws[(fb + 2) * HIDDEN + gb + 3] + s3 * Ws[(fb + 3) * HIDDEN + gb + 3];
    }
    ((uint2*)&g_hh[nxt][n * HIDDEN])[q] = pack4(o0, o1, o2, o3);
}

// Fused last layer: aggregate + bias + warp-segmented pool (batch is sorted).
__global__ void k_agg_pool(int cur, const float* __restrict__ b3,
                           const void* __restrict__ batch) {
    int idx = blockIdx.x * blockDim.x + threadIdx.x;
    int n = idx >> 2, q = idx & 3;
    if (n >= N_NODES) return;               // whole-warp exit
    int lane = threadIdx.x & 31;
    const uint2* h4 = (const uint2*)g_hh[cur];
    float di = g_dinv[n];
    float4 hv = unpack4(h4[n * 4 + q]);
    float s2 = di * di;
    float4 acc;
    acc.x = s2 * hv.x; acc.y = s2 * hv.y; acc.z = s2 * hv.z; acc.w = s2 * hv.w;
    int beg = g_off[n], end = g_off[n + 1];
#pragma unroll 4
    for (int e = beg; e < end; e++) {
        int2 sw = g_csr[e];
        float w = __int_as_float(sw.y);
        float4 v = unpack4(h4[sw.x * 4 + q]);
        acc.x += w * v.x; acc.y += w * v.y; acc.z += w * v.z; acc.w += w * v.w;
    }
    float4 bb = ((const float4*)b3)[q];
    acc.x += bb.x; acc.y += bb.y; acc.z += bb.z; acc.w += bb.w;
    int gph = read_idx(batch, n);
    // segmented tree-reduce across same-quarter lanes (stride 4) with equal gph.
    // batch sorted -> equal-gph lanes contiguous in the warp.
#pragma unroll
    for (int s = 4; s < 32; s <<= 1) {
        float ox = __shfl_down_sync(0xffffffffu, acc.x, s);
        float oy = __shfl_down_sync(0xffffffffu, acc.y, s);
        float oz = __shfl_down_sync(0xffffffffu, acc.z, s);
        float ow = __shfl_down_sync(0xffffffffu, acc.w, s);
        int   og = __shfl_down_sync(0xffffffffu, gph, s);
        if (lane + s < 32 && og == gph) {
            acc.x += ox; acc.y += oy; acc.z += oz; acc.w += ow;
        }
    }
    int upg = __shfl_up_sync(0xffffffffu, gph, 4);
    bool leader = (lane < 4) || (upg != gph);
    if (leader && (unsigned)gph < N_GRAPHS)
        red_add_v4((float4*)&g_pooled[gph * HIDDEN + q * 4], acc);
}

// out[g][c] = pooled[g] @ Wlin + blin
__global__ void k_head(const float* __restrict__ Wlin,
                       const float* __restrict__ blin, float* __restrict__ out) {
    int idx = blockIdx.x * blockDim.x + threadIdx.x;
    if (idx >= N_GRAPHS * N_CLASSES) return;
    int g = idx / N_CLASSES, c = idx % N_CLASSES;
    float s = blin[c];
#pragma unroll
    for (int f = 0; f < HIDDEN; f++)
        s += g_pooled[g * HIDDEN + f] * Wlin[f * N_CLASSES + c];
    out[idx] = s;
}

// ---------------- launch ----------------
extern "C" void kernel_launch(void* const* d_in, const int* in_sizes, int n_in,
                              void* d_out, int out_size) {
    const float* x     = (const float*)d_in[0];
    const void*  ei    = d_in[1];
    const void*  batch = d_in[2];
    const float* W1    = (const float*)d_in[3];
    const float* b1    = (const float*)d_in[4];
    const float* W2    = (const float*)d_in[5];
    const float* b2    = (const float*)d_in[6];
    const float* W3    = (const float*)d_in[7];
    const float* b3    = (const float*)d_in[8];
    const float* Wlin  = (const float*)d_in[9];
    const float* blin  = (const float*)d_in[10];
    float* out = (float*)d_out;

    // side stream + events for fork/join (created once; host-side only, no device mem)
    static cudaStream_t s1 = nullptr;
    static cudaEvent_t  e0 = nullptr, e1 = nullptr;
    if (!s1) {
        cudaStreamCreateWithFlags(&s1, cudaStreamNonBlocking);
        cudaEventCreateWithFlags(&e0, cudaEventDisableTiming);
        cudaEventCreateWithFlags(&e1, cudaEventDisableTiming);
    }

    const int T = 256;
    int gN  = (N_NODES + T - 1) / T;
    int gE  = (N_EDGES + T - 1) / T;
    int gN4 = (N_NODES * 4 + T - 1) / T;

    // fork: gemm1 on s1, CSR build on main stream
    cudaEventRecord(e0, 0);
    cudaStreamWaitEvent(s1, e0, 0);
    k_gemm1<<<gN, T, 0, s1>>>(x, W1);
    cudaEventRecord(e1, s1);

    k_zero<<<gN, T>>>((const int*)ei);
    k_count<<<gE, T>>>(ei);
    k_scan1<<<NBLK, SCAN_B>>>();
    k_scan3<<<NBLK, SCAN_B>>>();
    k_fill<<<gE, T>>>(ei);

    // join: aggregates need both h0 (s1) and CSR (main)
    cudaStreamWaitEvent(0, e1, 0);

    k_agg_update<<<gN4, T>>>(0, 1, b1, W2);
    k_agg_update<<<gN4, T>>>(1, 0, b2, W3);
    k_agg_pool<<<gN4, T>>>(0, b3, batch);
    k_head<<<(N_GRAPHS * N_CLASSES + T - 1) / T, T>>>(Wlin, blin, out);
}

// round 7
// speedup vs baseline: 2.3554x; 1.0189x over previous
#include <cuda_runtime.h>
#include <cuda_bf16.h>
#include <cuda_fp16.h>
#include <cstdint>

#define N_NODES   100000
#define N_EDGES   3200000
#define N_FEAT    128
#define HIDDEN    16
#define N_CLASSES 10
#define N_GRAPHS  512

#define SCAN_B 1024
#define NBLK   ((N_NODES + SCAN_B - 1) / SCAN_B)   // 98

// ---------------- scratch (static __device__; no allocation) ----------------
__device__ __align__(16) int2   g_csr[N_EDGES];        // {src, w-as-int}
__device__ __align__(16) int    g_off[N_NODES + 1];
__device__ __align__(16) int    g_cursor[N_NODES];
__device__ __align__(16) int    g_cnt[N_NODES];
__device__ __align__(16) int    g_bsum[NBLK];
__device__ __align__(16) float  g_dinv[N_NODES];
__device__ __align__(16) __half g_hh[2][N_NODES * HIDDEN];   // fp16 activations
__device__ __align__(16) float  g_pooled[N_GRAPHS * HIDDEN];
__device__ int g_is64;

// ---------------- helpers ----------------
__device__ __forceinline__ void red_add_v4(float4* addr, float4 v) {
    asm volatile("red.global.add.v4.f32 [%0], {%1,%2,%3,%4};"
                 :: "l"(addr), "f"(v.x), "f"(v.y), "f"(v.z), "f"(v.w)
                 : "memory");
}

__device__ __forceinline__ int read_idx(const void* p, long long j) {
    if (g_is64) return (int)((const long long*)p)[j];
    return ((const int*)p)[j];
}

__device__ __forceinline__ uint2 pack4(float a, float b, float c, float d) {
    __half2 lo = __floats2half2_rn(a, b), hi = __floats2half2_rn(c, d);
    uint2 r;
    r.x = *(unsigned*)&lo; r.y = *(unsigned*)&hi;
    return r;
}

__device__ __forceinline__ float4 unpack4(uint2 u) {
    __half2 lo = *(__half2*)&u.x, hi = *(__half2*)&u.y;
    float2 f0 = __half22float2(lo), f1 = __half22float2(hi);
    return make_float4(f0.x, f0.y, f1.x, f1.y);
}

// ---------------- preprocessing ----------------

// zero cnt + pooled; thread 0 also detects int64 vs int32 edge_index
__global__ void k_zero(const int* __restrict__ ei32) {
    int i = blockIdx.x * blockDim.x + threadIdx.x;
    if (i < N_NODES) g_cnt[i] = 0;
    if (i < N_GRAPHS * HIDDEN) g_pooled[i] = 0.f;
    if (i == 0) {
        int ok = 1;
        for (int j = 1; j < 128; j += 2)
            if (ei32[j] != 0) { ok = 0; break; }
        g_is64 = ok;
    }
}

// 4 edges per thread, vectorized dst read when int32
__global__ void k_count(const void* __restrict__ ei) {
    int t = blockIdx.x * blockDim.x + threadIdx.x;
    int base = t * 4;
    if (base >= N_EDGES) return;
    if (!g_is64) {
        const int4* dv = (const int4*)((const int*)ei + N_EDGES);
        int4 d = dv[t];
        if ((unsigned)d.x < N_NODES) atomicAdd(&g_cnt[d.x], 1);
        if ((unsigned)d.y < N_NODES) atomicAdd(&g_cnt[d.y], 1);
        if ((unsigned)d.z < N_NODES) atomicAdd(&g_cnt[d.z], 1);
        if ((unsigned)d.w < N_NODES) atomicAdd(&g_cnt[d.w], 1);
    } else {
        const long long* dp = (const long long*)ei + N_EDGES;
#pragma unroll
        for (int k = 0; k < 4; k++) {
            int d = (int)dp[base + k];
            if ((unsigned)d < N_NODES) atomicAdd(&g_cnt[d], 1);
        }
    }
}

// block-local exclusive scan of cnt -> off (local); bsum; dinv = rsqrt(cnt+1)
__global__ void k_scan1() {
    __shared__ int sh[SCAN_B];
    int i = blockIdx.x * SCAN_B + threadIdx.x;
    int v = (i < N_NODES) ? g_cnt[i] : 0;
    if (i < N_NODES) g_dinv[i] = rsqrtf((float)(v + 1));
    sh[threadIdx.x] = v;
    __syncthreads();
#pragma unroll
    for (int off = 1; off < SCAN_B; off <<= 1) {
        int t = (threadIdx.x >= off) ? sh[threadIdx.x - off] : 0;
        __syncthreads();
        sh[threadIdx.x] += t;
        __syncthreads();
    }
    if (i < N_NODES) g_off[i] = sh[threadIdx.x] - v;
    if (threadIdx.x == SCAN_B - 1) g_bsum[blockIdx.x] = sh[threadIdx.x];
}

// add block prefix (each block reduces bsum[0..blockIdx) itself); init cursor
__global__ void k_scan3() {          // grid NBLK, SCAN_B threads
    __shared__ int tmp[32];
    __shared__ int pfx;
    int t = threadIdx.x, j = blockIdx.x;
    int v = (t < j) ? g_bsum[t] : 0;     // j <= 97 < 1024
#pragma unroll
    for (int o = 16; o; o >>= 1) v += __shfl_down_sync(0xffffffffu, v, o);
    if ((t & 31) == 0) tmp[t >> 5] = v;
    __syncthreads();
    if (t < 32) {
        int s = tmp[t];
#pragma unroll
        for (int o = 16; o; o >>= 1) s += __shfl_down_sync(0xffffffffu, s, o);
        if (t == 0) pfx = s;
    }
    __syncthreads();
    int i = j * SCAN_B + t;
    if (i < N_NODES) {
        int o = g_off[i] + pfx;
        g_off[i] = o;
        g_cursor[i] = o;
    }
    if (i == 0) g_off[N_NODES] = N_EDGES;
}

// 4 edges per thread, vectorized src/dst reads when int32
__global__ void k_fill(const void* __restrict__ ei) {
    int t = blockIdx.x * blockDim.x + threadIdx.x;
    int base = t * 4;
    if (base >= N_EDGES) return;
    int ss[4], dd[4];
    if (!g_is64) {
        int4 s4 = ((const int4*)ei)[t];
        int4 d4 = ((const int4*)((const int*)ei + N_EDGES))[t];
        ss[0] = s4.x; ss[1] = s4.y; ss[2] = s4.z; ss[3] = s4.w;
        dd[0] = d4.x; dd[1] = d4.y; dd[2] = d4.z; dd[3] = d4.w;
    } else {
        const long long* sp = (const long long*)ei;
        const long long* dp = sp + N_EDGES;
#pragma unroll
        for (int k = 0; k < 4; k++) { ss[k] = (int)sp[base + k]; dd[k] = (int)dp[base + k]; }
    }
#pragma unroll
    for (int k = 0; k < 4; k++) {
        int s = ss[k], d = dd[k];
        if ((unsigned)s >= N_NODES) s = 0;
        if ((unsigned)d >= N_NODES) d = 0;
        int pos = atomicAdd(&g_cursor[d], 1);
        float w = g_dinv[s] * g_dinv[d];
        g_csr[pos] = make_int2(s, __float_as_int(w));
    }
}

// ---------------- compute ----------------

// h0 = x @ W1 (fp32 math, fp16 store). One thread per node. Runs on side stream.
__global__ void k_gemm1(const float* __restrict__ x, const float* __restrict__ W1) {
    __shared__ float Ws[N_FEAT * HIDDEN];
    for (int i = threadIdx.x; i < N_FEAT * HIDDEN; i += blockDim.x) Ws[i] = W1[i];
    __syncthreads();
    int n = blockIdx.x * blockDim.x + threadIdx.x;
    if (n >= N_NODES) return;
    const float4* xr = (const float4*)(x + (size_t)n * N_FEAT);
    const float4* W4 = (const float4*)Ws;
    float4 a0 = make_float4(0.f, 0.f, 0.f, 0.f), a1 = a0, a2 = a0, a3 = a0;
#pragma unroll 4
    for (int k4 = 0; k4 < N_FEAT / 4; k4++) {
        float4 v = xr[k4];
#pragma unroll
        for (int c = 0; c < 4; c++) {
            float xk = (c == 0) ? v.x : (c == 1) ? v.y : (c == 2) ? v.z : v.w;
            int row = (k4 * 4 + c) * 4;
            float4 w0 = W4[row + 0], w1 = W4[row + 1], w2 = W4[row + 2], w3 = W4[row + 3];
            a0.x += xk * w0.x; a0.y += xk * w0.y; a0.z += xk * w0.z; a0.w += xk * w0.w;
            a1.x += xk * w1.x; a1.y += xk * w1.y; a1.z += xk * w1.z; a1.w += xk * w1.w;
            a2.x += xk * w2.x; a2.y += xk * w2.y; a2.z += xk * w2.z; a2.w += xk * w2.w;
            a3.x += xk * w3.x; a3.y += xk * w3.y; a3.z += xk * w3.z; a3.w += xk * w3.w;
        }
    }
    uint2 u0 = pack4(a0.x, a0.y, a0.z, a0.w);
    uint2 u1 = pack4(a1.x, a1.y, a1.z, a1.w);
    uint2 u2 = pack4(a2.x, a2.y, a2.z, a2.w);
    uint2 u3 = pack4(a3.x, a3.y, a3.z, a3.w);
    uint4* ho = (uint4*)&g_hh[0][n * HIDDEN];
    ho[0] = make_uint4(u0.x, u0.y, u1.x, u1.y);
    ho[1] = make_uint4(u2.x, u2.y, u3.x, u3.y);
}

// 8-wide batched gather: load 8 csr entries, then 8 h rows (MLP ~16), then FMA.
__device__ __forceinline__ float4 agg_edges(const uint2* __restrict__ h4,
                                            int q, int beg, int end, float4 acc) {
    int e = beg;
    for (; e + 8 <= end; e += 8) {
        int2 c0 = g_csr[e + 0], c1 = g_csr[e + 1], c2 = g_csr[e + 2], c3 = g_csr[e + 3];
        int2 c4 = g_csr[e + 4], c5 = g_csr[e + 5], c6 = g_csr[e + 6], c7 = g_csr[e + 7];
        uint2 v0 = h4[c0.x * 4 + q], v1 = h4[c1.x * 4 + q];
        uint2 v2 = h4[c2.x * 4 + q], v3 = h4[c3.x * 4 + q];
        uint2 v4 = h4[c4.x * 4 + q], v5 = h4[c5.x * 4 + q];
        uint2 v6 = h4[c6.x * 4 + q], v7 = h4[c7.x * 4 + q];
#define ACC(ci, vi) { float w = __int_as_float(ci.y); float4 f = unpack4(vi); \
        acc.x += w * f.x; acc.y += w * f.y; acc.z += w * f.z; acc.w += w * f.w; }
        ACC(c0, v0) ACC(c1, v1) ACC(c2, v2) ACC(c3, v3)
        ACC(c4, v4) ACC(c5, v5) ACC(c6, v6) ACC(c7, v7)
    }
    for (; e < end; e++) {
        int2 sw = g_csr[e];
        float w = __int_as_float(sw.y);
        float4 f = unpack4(h4[sw.x * 4 + q]);
        acc.x += w * f.x; acc.y += w * f.y; acc.z += w * f.z; acc.w += w * f.w;
    }
#undef ACC
    return acc;
}

// Fused: agg = dinv^2*h[n] + sum_e w*h[src]; t = relu(agg+b); h_next = t @ W.
__global__ void k_agg_update(int cur, int nxt, const float* __restrict__ bias,
                             const float* __restrict__ Wn) {
    __shared__ float Ws[HIDDEN * HIDDEN];
    __shared__ float bs[HIDDEN];
    int t = threadIdx.x;
    if (t < HIDDEN * HIDDEN) Ws[t] = Wn[t];
    if (t < HIDDEN) bs[t] = bias[t];
    __syncthreads();
    int idx = blockIdx.x * blockDim.x + t;
    int n = idx >> 2, q = idx & 3;
    if (n >= N_NODES) return;               // whole-warp exit (400000 % 32 == 0)
    const uint2* h4 = (const uint2*)g_hh[cur];
    float di = g_dinv[n];
    float4 hv = unpack4(h4[n * 4 + q]);
    float s2 = di * di;
    float4 acc = make_float4(s2 * hv.x, s2 * hv.y, s2 * hv.z, s2 * hv.w);
    acc = agg_edges(h4, q, g_off[n], g_off[n + 1], acc);
    int gb = q * 4;
    float t0 = fmaxf(acc.x + bs[gb + 0], 0.f);
    float t1 = fmaxf(acc.y + bs[gb + 1], 0.f);
    float t2 = fmaxf(acc.z + bs[gb + 2], 0.f);
    float t3 = fmaxf(acc.w + bs[gb + 3], 0.f);
    float o0 = 0.f, o1 = 0.f, o2 = 0.f, o3 = 0.f;
#pragma unroll
    for (int r = 0; r < 4; r++) {
        float s0 = (r == 0) ? t0 : __shfl_xor_sync(0xffffffffu, t0, r);
        float s1 = (r == 0) ? t1 : __shfl_xor_sync(0xffffffffu, t1, r);
        float s2v = (r == 0) ? t2 : __shfl_xor_sync(0xffffffffu, t2, r);
        float s3 = (r == 0) ? t3 : __shfl_xor_sync(0xffffffffu, t3, r);
        int fb = (q ^ r) * 4;
        o0 += s0 * Ws[(fb + 0) * HIDDEN + gb + 0] + s1 * Ws[(fb + 1) * HIDDEN + gb + 0]
            + s2v * Ws[(fb + 2) * HIDDEN + gb + 0] + s3 * Ws[(fb + 3) * HIDDEN + gb + 0];
        o1 += s0 * Ws[(fb + 0) * HIDDEN + gb + 1] + s1 * Ws[(fb + 1) * HIDDEN + gb + 1]
            + s2v * Ws[(fb + 2) * HIDDEN + gb + 1] + s3 * Ws[(fb + 3) * HIDDEN + gb + 1];
        o2 += s0 * Ws[(fb + 0) * HIDDEN + gb + 2] + s1 * Ws[(fb + 1) * HIDDEN + gb + 2]
            + s2v * Ws[(fb + 2) * HIDDEN + gb + 2] + s3 * Ws[(fb + 3) * HIDDEN + gb + 2];
        o3 += s0 * Ws[(fb + 0) * HIDDEN + gb + 3] + s1 * Ws[(fb + 1) * HIDDEN + gb + 3]
            + s2v * Ws[(fb + 2) * HIDDEN + gb + 3] + s3 * Ws[(fb + 3) * HIDDEN + gb + 3];
    }
    ((uint2*)&g_hh[nxt][n * HIDDEN])[q] = pack4(o0, o1, o2, o3);
}

// Fused last layer: aggregate + bias + warp-segmented pool (batch is sorted).
__global__ void k_agg_pool(int cur, const float* __restrict__ b3,
                           const void* __restrict__ batch) {
    int idx = blockIdx.x * blockDim.x + threadIdx.x;
    int n = idx >> 2, q = idx & 3;
    if (n >= N_NODES) return;               // whole-warp exit
    int lane = threadIdx.x & 31;
    const uint2* h4 = (const uint2*)g_hh[cur];
    float di = g_dinv[n];
    float4 hv = unpack4(h4[n * 4 + q]);
    float s2 = di * di;
    float4 acc = make_float4(s2 * hv.x, s2 * hv.y, s2 * hv.z, s2 * hv.w);
    acc = agg_edges(h4, q, g_off[n], g_off[n + 1], acc);
    float4 bb = ((const float4*)b3)[q];
    acc.x += bb.x; acc.y += bb.y; acc.z += bb.z; acc.w += bb.w;
    int gph = read_idx(batch, n);
    // segmented tree-reduce across same-quarter lanes (stride 4) with equal gph
#pragma unroll
    for (int s = 4; s < 32; s <<= 1) {
        float ox = __shfl_down_sync(0xffffffffu, acc.x, s);
        float oy = __shfl_down_sync(0xffffffffu, acc.y, s);
        float oz = __shfl_down_sync(0xffffffffu, acc.z, s);
        float ow = __shfl_down_sync(0xffffffffu, acc.w, s);
        int   og = __shfl_down_sync(0xffffffffu, gph, s);
        if (lane + s < 32 && og == gph) {
            acc.x += ox; acc.y += oy; acc.z += oz; acc.w += ow;
        }
    }
    int upg = __shfl_up_sync(0xffffffffu, gph, 4);
    bool leader = (lane < 4) || (upg != gph);
    if (leader && (unsigned)gph < N_GRAPHS)
        red_add_v4((float4*)&g_pooled[gph * HIDDEN + q * 4], acc);
}

// out[g][c] = pooled[g] @ Wlin + blin
__global__ void k_head(const float* __restrict__ Wlin,
                       const float* __restrict__ blin, float* __restrict__ out) {
    int idx = blockIdx.x * blockDim.x + threadIdx.x;
    if (idx >= N_GRAPHS * N_CLASSES) return;
    int g = idx / N_CLASSES, c = idx % N_CLASSES;
    float s = blin[c];
#pragma unroll
    for (int f = 0; f < HIDDEN; f++)
        s += g_pooled[g * HIDDEN + f] * Wlin[f * N_CLASSES + c];
    out[idx] = s;
}

// ---------------- launch ----------------
extern "C" void kernel_launch(void* const* d_in, const int* in_sizes, int n_in,
                              void* d_out, int out_size) {
    const float* x     = (const float*)d_in[0];
    const void*  ei    = d_in[1];
    const void*  batch = d_in[2];
    const float* W1    = (const float*)d_in[3];
    const float* b1    = (const float*)d_in[4];
    const float* W2    = (const float*)d_in[5];
    const float* b2    = (const float*)d_in[6];
    const float* W3    = (const float*)d_in[7];
    const float* b3    = (const float*)d_in[8];
    const float* Wlin  = (const float*)d_in[9];
    const float* blin  = (const float*)d_in[10];
    float* out = (float*)d_out;

    static cudaStream_t s1 = nullptr;
    static cudaEvent_t  e0 = nullptr, e1 = nullptr;
    if (!s1) {
        cudaStreamCreateWithFlags(&s1, cudaStreamNonBlocking);
        cudaEventCreateWithFlags(&e0, cudaEventDisableTiming);
        cudaEventCreateWithFlags(&e1, cudaEventDisableTiming);
    }

    const int T = 256;
    int gN  = (N_NODES + T - 1) / T;
    int gE4 = (N_EDGES / 4 + T - 1) / T;
    int gN4 = (N_NODES * 4 + T - 1) / T;

    // fork: gemm1 on s1, CSR build on main stream
    cudaEventRecord(e0, 0);
    cudaStreamWaitEvent(s1, e0, 0);
    k_gemm1<<<gN, T, 0, s1>>>(x, W1);
    cudaEventRecord(e1, s1);

    k_zero<<<gN, T>>>((const int*)ei);
    k_count<<<gE4, T>>>(ei);
    k_scan1<<<NBLK, SCAN_B>>>();
    k_scan3<<<NBLK, SCAN_B>>>();
    k_fill<<<gE4, T>>>(ei);

    // join: aggregates need both h0 (s1) and CSR (main)
    cudaStreamWaitEvent(0, e1, 0);

    k_agg_update<<<gN4, T>>>(0, 1, b1, W2);
    k_agg_update<<<gN4, T>>>(1, 0, b2, W3);
    k_agg_pool<<<gN4, T>>>(0, b3, batch);
    k_head<<<(N_GRAPHS * N_CLASSES + T - 1) / T, T>>>(Wlin, blin, out);
}